// round 4
// baseline (speedup 1.0000x reference)
#include <cuda_runtime.h>

#define BATCH 2
#define SEQ   2048
#define DM    1024
#define NH    16
#define DK    64
#define MT    (BATCH*SEQ)   // 4096 total rows

// Scratch (allocation-free): 4 x 16 MB fp32, referenced ONLY from device code
__device__ float g_Qp[(size_t)MT*DM];
__device__ float g_Kp[(size_t)MT*DM];
__device__ float g_Vp[(size_t)MT*DM];
__device__ float g_Oh[(size_t)MT*DM];

// ---------------------------------------------------------------------------
// C[M,N] = A[M,K] @ W[N,K]^T + bias[N]
// dstSel: 0->g_Qp, 1->g_Kp, 2->g_Vp, 3->outPtr. srcSel: 0->A param, 1->g_Oh.
// 64x64 tile, 256 threads, 4x4 per thread, K-chunk 16. M=MT, N=K=DM fixed.
// ---------------------------------------------------------------------------
__global__ __launch_bounds__(256) void proj_kernel(
    const float* __restrict__ Ain, const float* __restrict__ W,
    const float* __restrict__ bias, float* __restrict__ outPtr,
    int srcSel, int dstSel)
{
    const float* A = (srcSel == 0) ? Ain : (const float*)g_Oh;
    float* C = (dstSel == 0) ? g_Qp : (dstSel == 1) ? g_Kp
             : (dstSel == 2) ? g_Vp : outPtr;

    __shared__ float As[64][17];
    __shared__ float Ws[64][17];
    const int tid = threadIdx.x;
    const int tx = tid & 15, ty = tid >> 4;
    const int row0 = blockIdx.y * 64, col0 = blockIdx.x * 64;

    float acc[4][4] = {};
    const int r = tid >> 2;          // 0..63
    const int c = (tid & 3) * 4;     // 0,4,8,12

    for (int kt = 0; kt < DM; kt += 16) {
        float4 va = *(const float4*)(A + (size_t)(row0 + r) * DM + kt + c);
        As[r][c] = va.x; As[r][c+1] = va.y; As[r][c+2] = va.z; As[r][c+3] = va.w;
        float4 vw = *(const float4*)(W + (size_t)(col0 + r) * DM + kt + c);
        Ws[r][c] = vw.x; Ws[r][c+1] = vw.y; Ws[r][c+2] = vw.z; Ws[r][c+3] = vw.w;
        __syncthreads();
        #pragma unroll
        for (int k = 0; k < 16; k++) {
            float a[4], w[4];
            #pragma unroll
            for (int i = 0; i < 4; i++) a[i] = As[ty*4+i][k];
            #pragma unroll
            for (int j = 0; j < 4; j++) w[j] = Ws[tx*4+j][k];
            #pragma unroll
            for (int i = 0; i < 4; i++)
                #pragma unroll
                for (int j = 0; j < 4; j++) acc[i][j] += a[i] * w[j];
        }
        __syncthreads();
    }
    #pragma unroll
    for (int i = 0; i < 4; i++) {
        const int rr = row0 + ty*4 + i;
        #pragma unroll
        for (int j = 0; j < 4; j++) {
            const int cc = col0 + tx*4 + j;
            C[(size_t)rr * DM + cc] = acc[i][j] + bias[cc];
        }
    }
}

// ---------------------------------------------------------------------------
// scores[bh][q][k] = dot(Qh[q,:], Kh[k,:]) / 8, written into attn region
// ---------------------------------------------------------------------------
__global__ __launch_bounds__(256) void scores_kernel(float* __restrict__ attn)
{
    const int bh = blockIdx.z;
    const int b = bh >> 4, h = bh & 15;
    const float* Aq = g_Qp + (size_t)b * SEQ * DM + h * DK;   // row stride DM
    const float* Ak = g_Kp + (size_t)b * SEQ * DM + h * DK;
    float* C = attn + (size_t)bh * SEQ * SEQ;

    __shared__ float As[64][17];
    __shared__ float Bs[64][17];
    const int tid = threadIdx.x;
    const int tx = tid & 15, ty = tid >> 4;
    const int row0 = blockIdx.y * 64, col0 = blockIdx.x * 64;
    const int r = tid >> 2;
    const int c = (tid & 3) * 4;

    float acc[4][4] = {};
    for (int kt = 0; kt < DK; kt += 16) {
        float4 va = *(const float4*)(Aq + (size_t)(row0 + r) * DM + kt + c);
        As[r][c] = va.x; As[r][c+1] = va.y; As[r][c+2] = va.z; As[r][c+3] = va.w;
        float4 vb = *(const float4*)(Ak + (size_t)(col0 + r) * DM + kt + c);
        Bs[r][c] = vb.x; Bs[r][c+1] = vb.y; Bs[r][c+2] = vb.z; Bs[r][c+3] = vb.w;
        __syncthreads();
        #pragma unroll
        for (int k = 0; k < 16; k++) {
            float a[4], w[4];
            #pragma unroll
            for (int i = 0; i < 4; i++) a[i] = As[ty*4+i][k];
            #pragma unroll
            for (int j = 0; j < 4; j++) w[j] = Bs[tx*4+j][k];
            #pragma unroll
            for (int i = 0; i < 4; i++)
                #pragma unroll
                for (int j = 0; j < 4; j++) acc[i][j] += a[i] * w[j];
        }
        __syncthreads();
    }
    #pragma unroll
    for (int i = 0; i < 4; i++) {
        const int rr = row0 + ty*4 + i;
        #pragma unroll
        for (int j = 0; j < 4; j++)
            C[(size_t)rr * SEQ + col0 + tx*4 + j] = acc[i][j] * 0.125f;
    }
}

// ---------------------------------------------------------------------------
// In-place row softmax over attn rows of length SEQ=2048. One block per row.
// ---------------------------------------------------------------------------
__global__ __launch_bounds__(256) void softmax_kernel(float* __restrict__ attn)
{
    float* p = attn + (size_t)blockIdx.x * SEQ;
    const int tid = threadIdx.x;
    const int lane = tid & 31, warp = tid >> 5;
    __shared__ float red[8];

    float v[8];
    float mx = -1e30f;
    #pragma unroll
    for (int i = 0; i < 8; i++) { v[i] = p[tid + 256*i]; mx = fmaxf(mx, v[i]); }
    #pragma unroll
    for (int o = 16; o; o >>= 1) mx = fmaxf(mx, __shfl_xor_sync(0xffffffffu, mx, o));
    if (lane == 0) red[warp] = mx;
    __syncthreads();
    mx = red[0];
    #pragma unroll
    for (int i = 1; i < 8; i++) mx = fmaxf(mx, red[i]);
    __syncthreads();

    float s = 0.f;
    #pragma unroll
    for (int i = 0; i < 8; i++) { v[i] = __expf(v[i] - mx); s += v[i]; }
    #pragma unroll
    for (int o = 16; o; o >>= 1) s += __shfl_xor_sync(0xffffffffu, s, o);
    if (lane == 0) red[warp] = s;
    __syncthreads();
    s = red[0];
    #pragma unroll
    for (int i = 1; i < 8; i++) s += red[i];
    const float inv = 1.f / s;
    #pragma unroll
    for (int i = 0; i < 8; i++) p[tid + 256*i] = v[i] * inv;
}

// ---------------------------------------------------------------------------
// g_Oh[b*S+q, h*64+d] = sum_k attn[bh][q][k] * g_Vp[b*S+k, h*64+d]
// ---------------------------------------------------------------------------
__global__ __launch_bounds__(256) void av_kernel(const float* __restrict__ attn)
{
    const int bh = blockIdx.z;
    const int b = bh >> 4, h = bh & 15;
    const float* A = attn + (size_t)bh * SEQ * SEQ;            // [S,S]
    const float* V = g_Vp + (size_t)b * SEQ * DM + h * DK;     // row stride DM
    float* C = g_Oh + (size_t)b * SEQ * DM + h * DK;

    __shared__ float As[64][17];
    __shared__ float Vs[16][68];
    const int tid = threadIdx.x;
    const int tx = tid & 15, ty = tid >> 4;
    const int row0 = blockIdx.y * 64;
    const int r  = tid >> 2;
    const int c  = (tid & 3) * 4;
    const int r2 = tid >> 4;          // 0..15
    const int c2 = (tid & 15) * 4;    // 0..60

    float acc[4][4] = {};
    for (int kt = 0; kt < SEQ; kt += 16) {
        float4 va = *(const float4*)(A + (size_t)(row0 + r) * SEQ + kt + c);
        As[r][c] = va.x; As[r][c+1] = va.y; As[r][c+2] = va.z; As[r][c+3] = va.w;
        float4 vv = *(const float4*)(V + (size_t)(kt + r2) * DM + c2);
        Vs[r2][c2] = vv.x; Vs[r2][c2+1] = vv.y; Vs[r2][c2+2] = vv.z; Vs[r2][c2+3] = vv.w;
        __syncthreads();
        #pragma unroll
        for (int k = 0; k < 16; k++) {
            float a[4], w[4];
            #pragma unroll
            for (int i = 0; i < 4; i++) a[i] = As[ty*4+i][k];
            #pragma unroll
            for (int j = 0; j < 4; j++) w[j] = Vs[k][tx*4+j];
            #pragma unroll
            for (int i = 0; i < 4; i++)
                #pragma unroll
                for (int j = 0; j < 4; j++) acc[i][j] += a[i] * w[j];
        }
        __syncthreads();
    }
    #pragma unroll
    for (int i = 0; i < 4; i++) {
        const int rr = row0 + ty*4 + i;
        #pragma unroll
        for (int j = 0; j < 4; j++)
            C[(size_t)rr * DM + tx*4 + j] = acc[i][j];
    }
}

// ---------------------------------------------------------------------------
extern "C" void kernel_launch(void* const* d_in, const int* in_sizes, int n_in,
                              void* d_out, int out_size)
{
    const float* q  = (const float*)d_in[0];
    const float* k  = (const float*)d_in[1];
    const float* v  = (const float*)d_in[2];
    const float* wq = (const float*)d_in[3];
    const float* bq = (const float*)d_in[4];
    const float* wk = (const float*)d_in[5];
    const float* bk = (const float*)d_in[6];
    const float* wv = (const float*)d_in[7];
    const float* bv = (const float*)d_in[8];
    const float* wo = (const float*)d_in[9];
    const float* bo = (const float*)d_in[10];

    float* out  = (float*)d_out;                       // [B,S,D]
    float* attn = out + (size_t)MT * DM;               // [B,H,S,S]

    const dim3 gproj(DM / 64, MT / 64);
    proj_kernel<<<gproj, 256>>>(q, wq, bq, nullptr, 0, 0);  // -> g_Qp
    proj_kernel<<<gproj, 256>>>(k, wk, bk, nullptr, 0, 1);  // -> g_Kp
    proj_kernel<<<gproj, 256>>>(v, wv, bv, nullptr, 0, 2);  // -> g_Vp

    scores_kernel<<<dim3(SEQ/64, SEQ/64, BATCH*NH), 256>>>(attn);
    softmax_kernel<<<BATCH*NH*SEQ, 256>>>(attn);
    av_kernel<<<dim3(1, SEQ/64, BATCH*NH), 256>>>(attn);

    proj_kernel<<<gproj, 256>>>(nullptr, wo, bo, out, 1, 3); // g_Oh -> out
}

// round 6
// speedup vs baseline: 1.8061x; 1.8061x over previous
#include <cuda_runtime.h>
#include <cuda_bf16.h>
#include <cstdint>

#define BATCH 2
#define SEQ   2048
#define DM    1024
#define NH    16
#define DK    64
#define MT    (BATCH*SEQ)   // 4096 total rows

#define BK    32
#define SSTR  40            // smem row stride in bf16 elements (32 data + 8 pad)

// Scratch (allocation-free), referenced ONLY from device code
__device__ float g_Qp[(size_t)MT*DM];
__device__ float g_Kp[(size_t)MT*DM];
__device__ float g_Vp[(size_t)MT*DM];
__device__ float g_Oh[(size_t)MT*DM];

// ---------------------------------------------------------------------------
__device__ __forceinline__ void mma_bf16(
    float& d0, float& d1, float& d2, float& d3,
    uint32_t a0, uint32_t a1, uint32_t a2, uint32_t a3,
    uint32_t b0, uint32_t b1)
{
    asm volatile(
        "mma.sync.aligned.m16n8k16.row.col.f32.bf16.bf16.f32 "
        "{%0,%1,%2,%3}, {%4,%5,%6,%7}, {%8,%9}, {%0,%1,%2,%3};"
        : "+f"(d0), "+f"(d1), "+f"(d2), "+f"(d3)
        : "r"(a0), "r"(a1), "r"(a2), "r"(a3), "r"(b0), "r"(b1));
}

__device__ __forceinline__ uint32_t pack_bf16(__nv_bfloat16 lo, __nv_bfloat16 hi)
{
    return (uint32_t)__bfloat16_as_ushort(lo) |
           ((uint32_t)__bfloat16_as_ushort(hi) << 16);
}

// split x,y (k-adjacent pair) into packed hi and lo bf16x2
__device__ __forceinline__ void cvt_hilo(float x, float y, uint32_t& h, uint32_t& l)
{
    __nv_bfloat16 hx = __float2bfloat16(x);
    __nv_bfloat16 hy = __float2bfloat16(y);
    __nv_bfloat16 lx = __float2bfloat16(x - __bfloat162float(hx));
    __nv_bfloat16 ly = __float2bfloat16(y - __bfloat162float(hy));
    h = pack_bf16(hx, hy);
    l = pack_bf16(lx, ly);
}

// ---------------------------------------------------------------------------
// Generic bf16x3 tensor-core GEMM core.
// C[M,N] = alpha * A[M,K] @ B^T + bias, with B stored:
//   TRANSB=false: B[n][k], k contiguous, row stride ldb  (weights / K-proj)
//   TRANSB=true : B[k][n], n contiguous, row stride ldb  (V in AV product)
// Block tile BM x BN, K-chunk 32. NT threads = (BM/64)*(BN/32)*32.
// Warp tile 64x32 (4 m-tiles x 4 n-tiles of m16n8k16).
// ---------------------------------------------------------------------------
template<int BM, int BN, int NT, bool TRANSB>
__device__ __forceinline__ void gemm_core(
    const float* __restrict__ A, int lda,
    const float* __restrict__ B, int ldb,
    float* __restrict__ C, int ldc,
    int K, float alpha, const float* __restrict__ bias)
{
    constexpr int WGM = BM / 64;
    __shared__ __nv_bfloat16 Ah[BM * SSTR], Al[BM * SSTR];
    __shared__ __nv_bfloat16 Bh[BN * SSTR], Bl[BN * SSTR];

    const int tid  = threadIdx.x;
    const int wid  = tid >> 5, lane = tid & 31;
    const int wm   = wid % WGM;          // warp row
    const int wn   = wid / WGM;          // warp col
    const int qr   = lane >> 2;          // 0..7
    const int qk   = lane & 3;           // 0..3
    const int row0 = blockIdx.y * BM;
    const int col0 = blockIdx.x * BN;

    float acc[4][4][4];
    #pragma unroll
    for (int i = 0; i < 4; i++)
        #pragma unroll
        for (int j = 0; j < 4; j++)
            #pragma unroll
            for (int d = 0; d < 4; d++) acc[i][j][d] = 0.f;

    const uint32_t* pAh = (const uint32_t*)Ah;
    const uint32_t* pAl = (const uint32_t*)Al;
    const uint32_t* pBh = (const uint32_t*)Bh;
    const uint32_t* pBl = (const uint32_t*)Bl;

    for (int kt = 0; kt < K; kt += BK) {
        // ---- fill A tile (BM x 32 fp32 -> hi/lo bf16 smem) ----
        #pragma unroll
        for (int it = 0; it < (BM * 8) / NT; it++) {
            int idx = tid + it * NT;
            int r = idx >> 3, c4 = (idx & 7) * 4;
            float4 v = *(const float4*)(A + (size_t)(row0 + r) * lda + kt + c4);
            uint32_t h0, l0, h1, l1;
            cvt_hilo(v.x, v.y, h0, l0);
            cvt_hilo(v.z, v.w, h1, l1);
            *(uint32_t*)&Ah[r * SSTR + c4]     = h0;
            *(uint32_t*)&Ah[r * SSTR + c4 + 2] = h1;
            *(uint32_t*)&Al[r * SSTR + c4]     = l0;
            *(uint32_t*)&Al[r * SSTR + c4 + 2] = l1;
        }
        // ---- fill B tile ----
        if (!TRANSB) {
            #pragma unroll
            for (int it = 0; it < (BN * 8) / NT; it++) {
                int idx = tid + it * NT;
                int r = idx >> 3, c4 = (idx & 7) * 4;
                float4 v = *(const float4*)(B + (size_t)(col0 + r) * ldb + kt + c4);
                uint32_t h0, l0, h1, l1;
                cvt_hilo(v.x, v.y, h0, l0);
                cvt_hilo(v.z, v.w, h1, l1);
                *(uint32_t*)&Bh[r * SSTR + c4]     = h0;
                *(uint32_t*)&Bh[r * SSTR + c4 + 2] = h1;
                *(uint32_t*)&Bl[r * SSTR + c4]     = l0;
                *(uint32_t*)&Bl[r * SSTR + c4 + 2] = l1;
            }
        } else {
            // B tile is [32 k][BN n] in gmem; transpose into Bh/Bl [n][k]
            #pragma unroll
            for (int it = 0; it < (BN * 8) / NT; it++) {
                int idx = tid + it * NT;
                int kr = idx / (BN / 4);
                int n0 = (idx % (BN / 4)) * 4;
                float4 v = *(const float4*)(B + (size_t)(kt + kr) * ldb + col0 + n0);
                float vv[4] = {v.x, v.y, v.z, v.w};
                #pragma unroll
                for (int i = 0; i < 4; i++) {
                    __nv_bfloat16 h = __float2bfloat16(vv[i]);
                    __nv_bfloat16 l = __float2bfloat16(vv[i] - __bfloat162float(h));
                    Bh[(n0 + i) * SSTR + kr] = h;
                    Bl[(n0 + i) * SSTR + kr] = l;
                }
            }
        }
        __syncthreads();

        // ---- MMA: 2 k-steps of 16 ----
        #pragma unroll
        for (int ks = 0; ks < 32; ks += 16) {
            uint32_t ah[4][4], al[4][4], bh[4][2], bl[4][2];
            const int cb = ks + qk * 2;
            #pragma unroll
            for (int mt = 0; mt < 4; mt++) {
                int r = wm * 64 + mt * 16 + qr;
                ah[mt][0] = pAh[(r * SSTR + cb) >> 1];
                ah[mt][1] = pAh[((r + 8) * SSTR + cb) >> 1];
                ah[mt][2] = pAh[(r * SSTR + cb + 8) >> 1];
                ah[mt][3] = pAh[((r + 8) * SSTR + cb + 8) >> 1];
                al[mt][0] = pAl[(r * SSTR + cb) >> 1];
                al[mt][1] = pAl[((r + 8) * SSTR + cb) >> 1];
                al[mt][2] = pAl[(r * SSTR + cb + 8) >> 1];
                al[mt][3] = pAl[((r + 8) * SSTR + cb + 8) >> 1];
            }
            #pragma unroll
            for (int nt = 0; nt < 4; nt++) {
                int n = wn * 32 + nt * 8 + qr;
                bh[nt][0] = pBh[(n * SSTR + cb) >> 1];
                bh[nt][1] = pBh[(n * SSTR + cb + 8) >> 1];
                bl[nt][0] = pBl[(n * SSTR + cb) >> 1];
                bl[nt][1] = pBl[(n * SSTR + cb + 8) >> 1];
            }
            #pragma unroll
            for (int mt = 0; mt < 4; mt++)
                #pragma unroll
                for (int nt = 0; nt < 4; nt++) {
                    float* d = acc[mt][nt];
                    mma_bf16(d[0], d[1], d[2], d[3],
                             ah[mt][0], ah[mt][1], ah[mt][2], ah[mt][3],
                             bh[nt][0], bh[nt][1]);
                    mma_bf16(d[0], d[1], d[2], d[3],
                             ah[mt][0], ah[mt][1], ah[mt][2], ah[mt][3],
                             bl[nt][0], bl[nt][1]);
                    mma_bf16(d[0], d[1], d[2], d[3],
                             al[mt][0], al[mt][1], al[mt][2], al[mt][3],
                             bh[nt][0], bh[nt][1]);
                }
        }
        __syncthreads();
    }

    // ---- epilogue ----
    #pragma unroll
    for (int mt = 0; mt < 4; mt++) {
        #pragma unroll
        for (int nt = 0; nt < 4; nt++) {
            int r = row0 + wm * 64 + mt * 16 + qr;
            int c = col0 + wn * 32 + nt * 8 + qk * 2;
            float b0 = bias ? bias[c]     : 0.f;
            float b1 = bias ? bias[c + 1] : 0.f;
            float* d = acc[mt][nt];
            C[(size_t)r * ldc + c]           = d[0] * alpha + b0;
            C[(size_t)r * ldc + c + 1]       = d[1] * alpha + b1;
            C[(size_t)(r + 8) * ldc + c]     = d[2] * alpha + b0;
            C[(size_t)(r + 8) * ldc + c + 1] = d[3] * alpha + b1;
        }
    }
}

// ---------------------------------------------------------------------------
// Projections: C = A @ W^T + bias.  srcSel: 0->Ain, 1->g_Oh.
// dstSel: 0->g_Qp, 1->g_Kp, 2->g_Vp, 3->outPtr
// ---------------------------------------------------------------------------
__global__ __launch_bounds__(256) void proj_kernel(
    const float* __restrict__ Ain, const float* __restrict__ W,
    const float* __restrict__ bias, float* __restrict__ outPtr,
    int srcSel, int dstSel)
{
    const float* A = (srcSel == 0) ? Ain : (const float*)g_Oh;
    float* C = (dstSel == 0) ? g_Qp : (dstSel == 1) ? g_Kp
             : (dstSel == 2) ? g_Vp : outPtr;
    gemm_core<128, 128, 256, false>(A, DM, W, DM, C, DM, DM, 1.0f, bias);
}

// scores[bh] = (Qh @ Kh^T) / 8  into attn region
__global__ __launch_bounds__(256) void scores_kernel(float* __restrict__ attn)
{
    const int bh = blockIdx.z;
    const int b = bh >> 4, h = bh & 15;
    const float* Aq = g_Qp + (size_t)b * SEQ * DM + h * DK;
    const float* Bk = g_Kp + (size_t)b * SEQ * DM + h * DK;
    float* C = attn + (size_t)bh * SEQ * SEQ;
    gemm_core<128, 128, 256, false>(Aq, DM, Bk, DM, C, SEQ, DK, 0.125f, nullptr);
}

// g_Oh[bh] = attn[bh] @ Vh   (V is [k][n] -> TRANSB)
__global__ __launch_bounds__(128) void av_kernel(const float* __restrict__ attn)
{
    const int bh = blockIdx.z;
    const int b = bh >> 4, h = bh & 15;
    const float* A = attn + (size_t)bh * SEQ * SEQ;
    const float* B = g_Vp + (size_t)b * SEQ * DM + h * DK;
    float* C = g_Oh + (size_t)b * SEQ * DM + h * DK;
    gemm_core<128, 64, 128, true>(A, SEQ, B, DM, C, DM, SEQ, 1.0f, nullptr);
}

// ---------------------------------------------------------------------------
// In-place row softmax over attn rows of length SEQ=2048. One block per row.
// ---------------------------------------------------------------------------
__global__ __launch_bounds__(256) void softmax_kernel(float* __restrict__ attn)
{
    float* p = attn + (size_t)blockIdx.x * SEQ;
    const int tid = threadIdx.x;
    const int lane = tid & 31, warp = tid >> 5;
    __shared__ float red[8];

    float v[8];
    float mx = -1e30f;
    #pragma unroll
    for (int i = 0; i < 8; i++) { v[i] = p[tid + 256*i]; mx = fmaxf(mx, v[i]); }
    #pragma unroll
    for (int o = 16; o; o >>= 1) mx = fmaxf(mx, __shfl_xor_sync(0xffffffffu, mx, o));
    if (lane == 0) red[warp] = mx;
    __syncthreads();
    mx = red[0];
    #pragma unroll
    for (int i = 1; i < 8; i++) mx = fmaxf(mx, red[i]);
    __syncthreads();

    float s = 0.f;
    #pragma unroll
    for (int i = 0; i < 8; i++) { v[i] = __expf(v[i] - mx); s += v[i]; }
    #pragma unroll
    for (int o = 16; o; o >>= 1) s += __shfl_xor_sync(0xffffffffu, s, o);
    if (lane == 0) red[warp] = s;
    __syncthreads();
    s = red[0];
    #pragma unroll
    for (int i = 1; i < 8; i++) s += red[i];
    const float inv = 1.f / s;
    #pragma unroll
    for (int i = 0; i < 8; i++) p[tid + 256*i] = v[i] * inv;
}

// ---------------------------------------------------------------------------
extern "C" void kernel_launch(void* const* d_in, const int* in_sizes, int n_in,
                              void* d_out, int out_size)
{
    const float* q  = (const float*)d_in[0];
    const float* k  = (const float*)d_in[1];
    const float* v  = (const float*)d_in[2];
    const float* wq = (const float*)d_in[3];
    const float* bq = (const float*)d_in[4];
    const float* wk = (const float*)d_in[5];
    const float* bk = (const float*)d_in[6];
    const float* wv = (const float*)d_in[7];
    const float* bv = (const float*)d_in[8];
    const float* wo = (const float*)d_in[9];
    const float* bo = (const float*)d_in[10];

    float* out  = (float*)d_out;                       // [B,S,D]
    float* attn = out + (size_t)MT * DM;               // [B,H,S,S]

    const dim3 gproj(DM / 128, MT / 128);              // (8, 32)
    proj_kernel<<<gproj, 256>>>(q, wq, bq, nullptr, 0, 0);   // -> g_Qp
    proj_kernel<<<gproj, 256>>>(k, wk, bk, nullptr, 0, 1);   // -> g_Kp
    proj_kernel<<<gproj, 256>>>(v, wv, bv, nullptr, 0, 2);   // -> g_Vp

    scores_kernel<<<dim3(SEQ/128, SEQ/128, BATCH*NH), 256>>>(attn);
    softmax_kernel<<<BATCH*NH*SEQ, 256>>>(attn);
    av_kernel<<<dim3(1, SEQ/128, BATCH*NH), 128>>>(attn);

    proj_kernel<<<gproj, 256>>>(nullptr, wo, bo, out, 1, 3); // g_Oh -> out
}

// round 8
// speedup vs baseline: 2.1853x; 1.2100x over previous
#include <cuda_runtime.h>
#include <cuda_bf16.h>
#include <cstdint>

#define BATCH 2
#define SEQ   2048
#define DM    1024
#define NH    16
#define DK    64
#define MT    (BATCH*SEQ)   // 4096 rows

typedef __nv_bfloat16 bf16;

constexpr size_t MB_   = 1024 * 1024;
constexpr size_t OFF_Q  = 0;
constexpr size_t OFF_K  = 4 * MB_;
constexpr size_t OFF_V  = 8 * MB_;
constexpr size_t OFF_WQ = 12 * MB_;
constexpr size_t OFF_WK = 13 * MB_;
constexpr size_t OFF_WV = 14 * MB_;
constexpr size_t OFF_WO = 15 * MB_;
constexpr size_t OFF_QP = 16 * MB_;
constexpr size_t OFF_KP = 20 * MB_;
constexpr size_t OFF_VP = 24 * MB_;
constexpr size_t OFF_OH = 28 * MB_;
constexpr size_t TOTEL  = 32 * MB_;

// Split (hi/lo bf16) scratch — device-side only
__device__ bf16 g_H[TOTEL];
__device__ bf16 g_L[TOTEL];
__device__ bf16 g_attnH[(size_t)BATCH * NH * SEQ * SEQ];
__device__ bf16 g_attnL[(size_t)BATCH * NH * SEQ * SEQ];

// ---------------------------------------------------------------------------
__device__ __forceinline__ uint32_t smem_u32(const void* p)
{
    return (uint32_t)__cvta_generic_to_shared(p);
}
#define CP16(dst, src) \
    asm volatile("cp.async.cg.shared.global [%0], [%1], 16;" :: "r"(dst), "l"(src))
#define CP_COMMIT() asm volatile("cp.async.commit_group;")
#define CP_WAIT1()  asm volatile("cp.async.wait_group 1;")
#define CP_WAIT0()  asm volatile("cp.async.wait_group 0;")

__device__ __forceinline__ void ldsm4(uint32_t* r, uint32_t a)
{
    asm volatile("ldmatrix.sync.aligned.m8n8.x4.shared.b16 {%0,%1,%2,%3}, [%4];"
                 : "=r"(r[0]), "=r"(r[1]), "=r"(r[2]), "=r"(r[3]) : "r"(a));
}
__device__ __forceinline__ void ldsm4t(uint32_t* r, uint32_t a)
{
    asm volatile("ldmatrix.sync.aligned.m8n8.x4.trans.shared.b16 {%0,%1,%2,%3}, [%4];"
                 : "=r"(r[0]), "=r"(r[1]), "=r"(r[2]), "=r"(r[3]) : "r"(a));
}
__device__ __forceinline__ void mma_bf16(
    float* d, const uint32_t* a, const uint32_t* b)
{
    asm volatile(
        "mma.sync.aligned.m16n8k16.row.col.f32.bf16.bf16.f32 "
        "{%0,%1,%2,%3}, {%4,%5,%6,%7}, {%8,%9}, {%0,%1,%2,%3};"
        : "+f"(d[0]), "+f"(d[1]), "+f"(d[2]), "+f"(d[3])
        : "r"(a[0]), "r"(a[1]), "r"(a[2]), "r"(a[3]), "r"(b[0]), "r"(b[1]));
}
__device__ __forceinline__ uint32_t pack2(float x, float y)
{
    __nv_bfloat162 t = __floats2bfloat162_rn(x, y);
    return *(uint32_t*)&t;
}

// ---------------------------------------------------------------------------
// bf16x3 GEMM: C = alpha*A@B^T (+bias). A,B pre-split hi/lo bf16.
//   TRANSB=false: B[n][k] k-contig.  TRANSB=true: B[k][n] n-contig (BN=64).
// BK=32, double-buffered cp.async, ldmatrix fragments, XOR swizzle.
// EPI 0: fp32 C.  EPI 1: split bf16 C (CH/CL).
// ---------------------------------------------------------------------------
template<int BM, int BN, int NT, bool TRANSB, int EPI>
__device__ __forceinline__ void gemm2(
    const bf16* __restrict__ AH, const bf16* __restrict__ AL, int lda,
    const bf16* __restrict__ BH, const bf16* __restrict__ BL, int ldb,
    float* __restrict__ Cf, bf16* __restrict__ CH, bf16* __restrict__ CL,
    int ldc, int K, float alpha, const float* __restrict__ bias)
{
    constexpr int WGM  = BM / 64;
    constexpr int ABUF = BM * 64;                       // bytes/buffer/array
    constexpr int BBUF = TRANSB ? 32 * BN * 2 : BN * 64;
    extern __shared__ char smem[];
    char* aHs = smem;
    char* aLs = aHs + 2 * ABUF;
    char* bHs = aLs + 2 * ABUF;
    char* bLs = bHs + 2 * BBUF;

    const int tid  = threadIdx.x;
    const int wid  = tid >> 5, lane = tid & 31;
    const int wm   = wid % WGM;
    const int wn   = wid / WGM;
    const int row0 = blockIdx.y * BM;
    const int col0 = blockIdx.x * BN;

    float acc[4][4][4];
    #pragma unroll
    for (int i = 0; i < 4; i++)
        #pragma unroll
        for (int j = 0; j < 4; j++)
            #pragma unroll
            for (int d = 0; d < 4; d++) acc[i][j][d] = 0.f;

    // per-lane ldmatrix geometry
    const int mA  = lane >> 3;                 // matrix id 0..3
    const int raL = (mA & 1) * 8 + (lane & 7); // A row within 16
    const int chA = lane >> 4;                 // k-chunk half 0/1

    auto fillA = [&](int kt, int buf) {
        constexpr int ACH = BM * 4;
        #pragma unroll
        for (int it = 0; it < (2 * ACH) / NT; it++) {
            int id  = tid + it * NT;
            int arr = id / ACH, id2 = id % ACH;
            int r = id2 >> 2, c = id2 & 3;
            const bf16* src = (arr ? AL : AH) + (size_t)(row0 + r) * lda + kt + c * 8;
            char* dst = (arr ? aLs : aHs) + buf * ABUF + r * 64 + ((c ^ ((r >> 1) & 3)) << 4);
            CP16(smem_u32(dst), src);
        }
    };
    auto fillB = [&](int kt, int buf) {
        if (!TRANSB) {
            constexpr int BCH = BN * 4;
            #pragma unroll
            for (int it = 0; it < (2 * BCH) / NT; it++) {
                int id  = tid + it * NT;
                int arr = id / BCH, id2 = id % BCH;
                int r = id2 >> 2, c = id2 & 3;
                const bf16* src = (arr ? BL : BH) + (size_t)(col0 + r) * ldb + kt + c * 8;
                char* dst = (arr ? bLs : bHs) + buf * BBUF + r * 64 + ((c ^ ((r >> 1) & 3)) << 4);
                CP16(smem_u32(dst), src);
            }
        } else {
            constexpr int NC  = BN / 8;
            constexpr int BCH = 32 * NC;
            #pragma unroll
            for (int it = 0; it < (2 * BCH) / NT; it++) {
                int id  = tid + it * NT;
                int arr = id / BCH, id2 = id % BCH;
                int r = id2 / NC, c = id2 % NC;
                const bf16* src = (arr ? BL : BH) + (size_t)(kt + r) * ldb + col0 + c * 8;
                char* dst = (arr ? bLs : bHs) + buf * BBUF + r * (BN * 2) + ((c ^ (r & 7)) << 4);
                CP16(smem_u32(dst), src);
            }
        }
    };

    const int nIter = K / 32;
    fillA(0, 0); fillB(0, 0); CP_COMMIT();

    for (int i = 0; i < nIter; i++) {
        const int buf = i & 1;
        if (i + 1 < nIter) {
            fillA((i + 1) * 32, buf ^ 1);
            fillB((i + 1) * 32, buf ^ 1);
            CP_COMMIT();
            CP_WAIT1();
        } else {
            CP_WAIT0();
        }
        __syncthreads();

        #pragma unroll
        for (int ks = 0; ks < 32; ks += 16) {
            const int kc = ks >> 3;
            uint32_t ah[4][4], al[4][4], bh[4][2], bl[4][2];
            #pragma unroll
            for (int mt = 0; mt < 4; mt++) {
                int r  = wm * 64 + mt * 16 + raL;
                int ca = kc + chA;
                int off = buf * ABUF + r * 64 + ((ca ^ ((r >> 1) & 3)) << 4);
                ldsm4(ah[mt], smem_u32(aHs + off));
                ldsm4(al[mt], smem_u32(aLs + off));
            }
            #pragma unroll
            for (int np = 0; np < 2; np++) {
                uint32_t t4[4], u4[4];
                if (!TRANSB) {
                    int n  = wn * 32 + np * 16 + raL;
                    int cb = kc + chA;
                    int off = buf * BBUF + n * 64 + ((cb ^ ((n >> 1) & 3)) << 4);
                    ldsm4(t4, smem_u32(bHs + off));
                    ldsm4(u4, smem_u32(bLs + off));
                } else {
                    int kr  = ks + chA * 8 + (lane & 7);
                    int nch = wn * 4 + np * 2 + (mA & 1);
                    int off = buf * BBUF + kr * (BN * 2) + ((nch ^ (kr & 7)) << 4);
                    ldsm4t(t4, smem_u32(bHs + off));
                    ldsm4t(u4, smem_u32(bLs + off));
                }
                bh[np*2][0]   = t4[0]; bh[np*2+1][0] = t4[1];
                bh[np*2][1]   = t4[2]; bh[np*2+1][1] = t4[3];
                bl[np*2][0]   = u4[0]; bl[np*2+1][0] = u4[1];
                bl[np*2][1]   = u4[2]; bl[np*2+1][1] = u4[3];
            }
            #pragma unroll
            for (int mt = 0; mt < 4; mt++)
                #pragma unroll
                for (int nt = 0; nt < 4; nt++) {
                    mma_bf16(acc[mt][nt], ah[mt], bh[nt]);
                    mma_bf16(acc[mt][nt], ah[mt], bl[nt]);
                    mma_bf16(acc[mt][nt], al[mt], bh[nt]);
                }
        }
        __syncthreads();
    }

    // epilogue
    const int qr = lane >> 2, qk = (lane & 3) * 2;
    #pragma unroll
    for (int mt = 0; mt < 4; mt++) {
        #pragma unroll
        for (int nt = 0; nt < 4; nt++) {
            int r = row0 + wm * 64 + mt * 16 + qr;
            int c = col0 + wn * 32 + nt * 8 + qk;
            float b0 = bias ? bias[c] : 0.f, b1 = bias ? bias[c + 1] : 0.f;
            float v0 = acc[mt][nt][0] * alpha + b0;
            float v1 = acc[mt][nt][1] * alpha + b1;
            float v2 = acc[mt][nt][2] * alpha + b0;
            float v3 = acc[mt][nt][3] * alpha + b1;
            if (EPI == 0) {
                *(float2*)&Cf[(size_t)r * ldc + c]       = make_float2(v0, v1);
                *(float2*)&Cf[(size_t)(r + 8) * ldc + c] = make_float2(v2, v3);
            } else {
                bf16 h0 = __float2bfloat16(v0), h1 = __float2bfloat16(v1);
                bf16 h2 = __float2bfloat16(v2), h3 = __float2bfloat16(v3);
                *(uint32_t*)&CH[(size_t)r * ldc + c] =
                    pack2(__bfloat162float(h0), __bfloat162float(h1));
                *(uint32_t*)&CH[(size_t)(r + 8) * ldc + c] =
                    pack2(__bfloat162float(h2), __bfloat162float(h3));
                *(uint32_t*)&CL[(size_t)r * ldc + c] =
                    pack2(v0 - __bfloat162float(h0), v1 - __bfloat162float(h1));
                *(uint32_t*)&CL[(size_t)(r + 8) * ldc + c] =
                    pack2(v2 - __bfloat162float(h2), v3 - __bfloat162float(h3));
            }
        }
    }
}

// ---------------------------------------------------------------------------
// fp32 -> hi/lo bf16 split convert
__global__ __launch_bounds__(256) void conv_kernel(
    const float4* __restrict__ src, int n4, size_t dstOff)
{
    int i = blockIdx.x * 256 + threadIdx.x;
    if (i >= n4) return;
    float4 v = src[i];
    bf16 h0 = __float2bfloat16(v.x), h1 = __float2bfloat16(v.y);
    bf16 h2 = __float2bfloat16(v.z), h3 = __float2bfloat16(v.w);
    uint32_t H0 = pack2(__bfloat162float(h0), __bfloat162float(h1));
    uint32_t H1 = pack2(__bfloat162float(h2), __bfloat162float(h3));
    uint32_t L0 = pack2(v.x - __bfloat162float(h0), v.y - __bfloat162float(h1));
    uint32_t L1 = pack2(v.z - __bfloat162float(h2), v.w - __bfloat162float(h3));
    *(uint2*)&g_H[dstOff + (size_t)i * 4] = make_uint2(H0, H1);
    *(uint2*)&g_L[dstOff + (size_t)i * 4] = make_uint2(L0, L1);
}

// ---------------------------------------------------------------------------
// proj: sel 0/1/2 = Q/K/V (split out), sel 3 = O (fp32 out)
__global__ __launch_bounds__(256, 1) void proj_kernel(
    const float* __restrict__ bias, int sel, float* __restrict__ outPtr)
{
    size_t aoff = sel == 0 ? OFF_Q : sel == 1 ? OFF_K : sel == 2 ? OFF_V : OFF_OH;
    size_t boff = sel == 0 ? OFF_WQ : sel == 1 ? OFF_WK : sel == 2 ? OFF_WV : OFF_WO;
    if (sel == 3) {
        gemm2<128, 128, 256, false, 0>(
            g_H + aoff, g_L + aoff, DM, g_H + boff, g_L + boff, DM,
            outPtr, nullptr, nullptr, DM, DM, 1.f, bias);
    } else {
        size_t coff = sel == 0 ? OFF_QP : sel == 1 ? OFF_KP : OFF_VP;
        gemm2<128, 128, 256, false, 1>(
            g_H + aoff, g_L + aoff, DM, g_H + boff, g_L + boff, DM,
            nullptr, g_H + coff, g_L + coff, DM, DM, 1.f, bias);
    }
}

// scores[bh] = (Qh @ Kh^T)/8 -> attn fp32
__global__ __launch_bounds__(256, 1) void scores_kernel(float* __restrict__ attn)
{
    const int bh = blockIdx.z, b = bh >> 4, h = bh & 15;
    const size_t s = (size_t)b * SEQ * DM + h * DK;
    gemm2<128, 128, 256, false, 0>(
        g_H + OFF_QP + s, g_L + OFF_QP + s, DM,
        g_H + OFF_KP + s, g_L + OFF_KP + s, DM,
        attn + (size_t)bh * SEQ * SEQ, nullptr, nullptr, SEQ,
        DK, 0.125f, nullptr);
}

// Oh[bh] = attnSplit[bh] @ Vh (TRANSB), split out
__global__ __launch_bounds__(128, 1) void av_kernel()
{
    const int bh = blockIdx.z, b = bh >> 4, h = bh & 15;
    const size_t sa = (size_t)bh * SEQ * SEQ;
    const size_t sv = (size_t)b * SEQ * DM + h * DK;
    gemm2<128, 64, 128, true, 1>(
        g_attnH + sa, g_attnL + sa, SEQ,
        g_H + OFF_VP + sv, g_L + OFF_VP + sv, DM,
        nullptr, g_H + OFF_OH + sv, g_L + OFF_OH + sv, DM,
        SEQ, 1.f, nullptr);
}

// ---------------------------------------------------------------------------
// softmax: in-place fp32 + split bf16 emit
__global__ __launch_bounds__(256) void softmax_kernel(float* __restrict__ attn)
{
    const size_t base = (size_t)blockIdx.x * SEQ;
    float* p = attn + base;
    const int tid = threadIdx.x;
    const int lane = tid & 31, warp = tid >> 5;
    __shared__ float red[8];

    float v[8];
    float mx = -1e30f;
    #pragma unroll
    for (int i = 0; i < 8; i++) { v[i] = p[tid + 256 * i]; mx = fmaxf(mx, v[i]); }
    #pragma unroll
    for (int o = 16; o; o >>= 1) mx = fmaxf(mx, __shfl_xor_sync(0xffffffffu, mx, o));
    if (lane == 0) red[warp] = mx;
    __syncthreads();
    mx = red[0];
    #pragma unroll
    for (int i = 1; i < 8; i++) mx = fmaxf(mx, red[i]);
    __syncthreads();

    float s = 0.f;
    #pragma unroll
    for (int i = 0; i < 8; i++) { v[i] = __expf(v[i] - mx); s += v[i]; }
    #pragma unroll
    for (int o = 16; o; o >>= 1) s += __shfl_xor_sync(0xffffffffu, s, o);
    if (lane == 0) red[warp] = s;
    __syncthreads();
    s = red[0];
    #pragma unroll
    for (int i = 1; i < 8; i++) s += red[i];
    const float inv = 1.f / s;
    #pragma unroll
    for (int i = 0; i < 8; i++) {
        float o = v[i] * inv;
        p[tid + 256 * i] = o;
        bf16 h = __float2bfloat16(o);
        g_attnH[base + tid + 256 * i] = h;
        g_attnL[base + tid + 256 * i] = __float2bfloat16(o - __bfloat162float(h));
    }
}

// ---------------------------------------------------------------------------
extern "C" void kernel_launch(void* const* d_in, const int* in_sizes, int n_in,
                              void* d_out, int out_size)
{
    const float* q  = (const float*)d_in[0];
    const float* k  = (const float*)d_in[1];
    const float* v  = (const float*)d_in[2];
    const float* wq = (const float*)d_in[3];
    const float* bq = (const float*)d_in[4];
    const float* wk = (const float*)d_in[5];
    const float* bk = (const float*)d_in[6];
    const float* wv = (const float*)d_in[7];
    const float* bv = (const float*)d_in[8];
    const float* wo = (const float*)d_in[9];
    const float* bo = (const float*)d_in[10];

    float* out  = (float*)d_out;
    float* attn = out + (size_t)MT * DM;

    static bool attrSet = false;
    if (!attrSet) {
        cudaFuncSetAttribute(proj_kernel,
            cudaFuncAttributeMaxDynamicSharedMemorySize, 65536);
        cudaFuncSetAttribute(scores_kernel,
            cudaFuncAttributeMaxDynamicSharedMemorySize, 65536);
        cudaFuncSetAttribute(av_kernel,
            cudaFuncAttributeMaxDynamicSharedMemorySize, 49152);
        attrSet = true;
    }

    const int nIn = MT * DM / 4;     // 1,048,576 float4
    const int nW  = DM * DM / 4;     // 262,144 float4
    conv_kernel<<<(nIn + 255) / 256, 256>>>((const float4*)q, nIn, OFF_Q);
    conv_kernel<<<(nIn + 255) / 256, 256>>>((const float4*)k, nIn, OFF_K);
    conv_kernel<<<(nIn + 255) / 256, 256>>>((const float4*)v, nIn, OFF_V);
    conv_kernel<<<(nW + 255) / 256, 256>>>((const float4*)wq, nW, OFF_WQ);
    conv_kernel<<<(nW + 255) / 256, 256>>>((const float4*)wk, nW, OFF_WK);
    conv_kernel<<<(nW + 255) / 256, 256>>>((const float4*)wv, nW, OFF_WV);
    conv_kernel<<<(nW + 255) / 256, 256>>>((const float4*)wo, nW, OFF_WO);

    const dim3 gproj(DM / 128, MT / 128);
    proj_kernel<<<gproj, 256, 65536>>>(bq, 0, nullptr);
    proj_kernel<<<gproj, 256, 65536>>>(bk, 1, nullptr);
    proj_kernel<<<gproj, 256, 65536>>>(bv, 2, nullptr);

    scores_kernel<<<dim3(SEQ / 128, SEQ / 128, BATCH * NH), 256, 65536>>>(attn);
    softmax_kernel<<<BATCH * NH * SEQ, 256>>>(attn);
    av_kernel<<<dim3(1, SEQ / 128, BATCH * NH), 128, 49152>>>();

    proj_kernel<<<gproj, 256, 65536>>>(bo, 3, out);
}

// round 9
// speedup vs baseline: 2.4257x; 1.1100x over previous
#include <cuda_runtime.h>
#include <cuda_bf16.h>
#include <cstdint>

#define BATCH 2
#define SEQ   2048
#define DM    1024
#define NH    16
#define DK    64
#define MT    (BATCH*SEQ)

typedef __nv_bfloat16 bf16;

constexpr size_t MB_   = 1024 * 1024;
constexpr size_t OFF_Q  = 0;
constexpr size_t OFF_K  = 4 * MB_;
constexpr size_t OFF_V  = 8 * MB_;
constexpr size_t OFF_WQ = 12 * MB_;
constexpr size_t OFF_QP = 16 * MB_;
constexpr size_t OFF_KP = 20 * MB_;
constexpr size_t OFF_VP = 24 * MB_;
constexpr size_t OFF_OH = 28 * MB_;
constexpr size_t TOTEL  = 32 * MB_;

__device__ bf16 g_H[TOTEL];
__device__ bf16 g_L[TOTEL];

// ---------------------------------------------------------------------------
__device__ __forceinline__ uint32_t smem_u32(const void* p)
{ return (uint32_t)__cvta_generic_to_shared(p); }
#define CP16(dst, src) \
    asm volatile("cp.async.cg.shared.global [%0], [%1], 16;" :: "r"(dst), "l"(src))
#define CP_COMMIT() asm volatile("cp.async.commit_group;")
#define CP_WAIT1()  asm volatile("cp.async.wait_group 1;")
#define CP_WAIT0()  asm volatile("cp.async.wait_group 0;")

__device__ __forceinline__ void ldsm4(uint32_t* r, uint32_t a)
{
    asm volatile("ldmatrix.sync.aligned.m8n8.x4.shared.b16 {%0,%1,%2,%3}, [%4];"
                 : "=r"(r[0]), "=r"(r[1]), "=r"(r[2]), "=r"(r[3]) : "r"(a));
}
__device__ __forceinline__ void ldsm4t(uint32_t* r, uint32_t a)
{
    asm volatile("ldmatrix.sync.aligned.m8n8.x4.trans.shared.b16 {%0,%1,%2,%3}, [%4];"
                 : "=r"(r[0]), "=r"(r[1]), "=r"(r[2]), "=r"(r[3]) : "r"(a));
}
__device__ __forceinline__ void mma_bf16(
    float* d, const uint32_t* a, const uint32_t* b)
{
    asm volatile(
        "mma.sync.aligned.m16n8k16.row.col.f32.bf16.bf16.f32 "
        "{%0,%1,%2,%3}, {%4,%5,%6,%7}, {%8,%9}, {%0,%1,%2,%3};"
        : "+f"(d[0]), "+f"(d[1]), "+f"(d[2]), "+f"(d[3])
        : "r"(a[0]), "r"(a[1]), "r"(a[2]), "r"(a[3]), "r"(b[0]), "r"(b[1]));
}
__device__ __forceinline__ uint32_t pack2(float x, float y)
{
    __nv_bfloat162 t = __floats2bfloat162_rn(x, y);
    return *(uint32_t*)&t;
}

// ---------------------------------------------------------------------------
// bf16x3 GEMM for projections (pre-split operands, cp.async double-buffer)
// ---------------------------------------------------------------------------
template<int BM, int BN, int NT, int EPI>
__device__ __forceinline__ void gemm2(
    const bf16* __restrict__ AH, const bf16* __restrict__ AL, int lda,
    const bf16* __restrict__ BH, const bf16* __restrict__ BL, int ldb,
    float* __restrict__ Cf, bf16* __restrict__ CH, bf16* __restrict__ CL,
    int ldc, int K, float alpha, const float* __restrict__ bias)
{
    constexpr int WGM  = BM / 64;
    constexpr int ABUF = BM * 64;
    constexpr int BBUF = BN * 64;
    extern __shared__ char smem[];
    char* aHs = smem;
    char* aLs = aHs + 2 * ABUF;
    char* bHs = aLs + 2 * ABUF;
    char* bLs = bHs + 2 * BBUF;

    const int tid  = threadIdx.x;
    const int wid  = tid >> 5, lane = tid & 31;
    const int wm   = wid % WGM;
    const int wn   = wid / WGM;
    const int row0 = blockIdx.y * BM;
    const int col0 = blockIdx.x * BN;

    float acc[4][4][4];
    #pragma unroll
    for (int i = 0; i < 4; i++)
        #pragma unroll
        for (int j = 0; j < 4; j++)
            #pragma unroll
            for (int d = 0; d < 4; d++) acc[i][j][d] = 0.f;

    const int raL = lane & 15;
    const int chA = lane >> 4;

    auto fillA = [&](int kt, int buf) {
        constexpr int ACH = BM * 4;
        #pragma unroll
        for (int it = 0; it < (2 * ACH) / NT; it++) {
            int id  = tid + it * NT;
            int arr = id / ACH, id2 = id % ACH;
            int r = id2 >> 2, c = id2 & 3;
            const bf16* src = (arr ? AL : AH) + (size_t)(row0 + r) * lda + kt + c * 8;
            char* dst = (arr ? aLs : aHs) + buf * ABUF + r * 64 + ((c ^ ((r >> 1) & 3)) << 4);
            CP16(smem_u32(dst), src);
        }
    };
    auto fillB = [&](int kt, int buf) {
        constexpr int BCH = BN * 4;
        #pragma unroll
        for (int it = 0; it < (2 * BCH) / NT; it++) {
            int id  = tid + it * NT;
            int arr = id / BCH, id2 = id % BCH;
            int r = id2 >> 2, c = id2 & 3;
            const bf16* src = (arr ? BL : BH) + (size_t)(col0 + r) * ldb + kt + c * 8;
            char* dst = (arr ? bLs : bHs) + buf * BBUF + r * 64 + ((c ^ ((r >> 1) & 3)) << 4);
            CP16(smem_u32(dst), src);
        }
    };

    const int nIter = K / 32;
    fillA(0, 0); fillB(0, 0); CP_COMMIT();

    for (int i = 0; i < nIter; i++) {
        const int buf = i & 1;
        if (i + 1 < nIter) {
            fillA((i + 1) * 32, buf ^ 1);
            fillB((i + 1) * 32, buf ^ 1);
            CP_COMMIT();
            CP_WAIT1();
        } else { CP_WAIT0(); }
        __syncthreads();

        #pragma unroll
        for (int ks = 0; ks < 32; ks += 16) {
            const int kc = ks >> 3;
            uint32_t ah[4][4], al[4][4], bh[4][2], bl[4][2];
            #pragma unroll
            for (int mt = 0; mt < 4; mt++) {
                int r  = wm * 64 + mt * 16 + raL;
                int ca = kc + chA;
                int off = buf * ABUF + r * 64 + ((ca ^ ((r >> 1) & 3)) << 4);
                ldsm4(ah[mt], smem_u32(aHs + off));
                ldsm4(al[mt], smem_u32(aLs + off));
            }
            #pragma unroll
            for (int np = 0; np < 2; np++) {
                uint32_t t4[4], u4[4];
                int n  = wn * 32 + np * 16 + raL;
                int cb = kc + chA;
                int off = buf * BBUF + n * 64 + ((cb ^ ((n >> 1) & 3)) << 4);
                ldsm4(t4, smem_u32(bHs + off));
                ldsm4(u4, smem_u32(bLs + off));
                bh[np*2][0]   = t4[0]; bh[np*2+1][0] = t4[1];
                bh[np*2][1]   = t4[2]; bh[np*2+1][1] = t4[3];
                bl[np*2][0]   = u4[0]; bl[np*2+1][0] = u4[1];
                bl[np*2][1]   = u4[2]; bl[np*2+1][1] = u4[3];
            }
            #pragma unroll
            for (int mt = 0; mt < 4; mt++)
                #pragma unroll
                for (int nt = 0; nt < 4; nt++) {
                    mma_bf16(acc[mt][nt], ah[mt], bh[nt]);
                    mma_bf16(acc[mt][nt], ah[mt], bl[nt]);
                    mma_bf16(acc[mt][nt], al[mt], bh[nt]);
                }
        }
        __syncthreads();
    }

    const int qr = lane >> 2, qk = (lane & 3) * 2;
    #pragma unroll
    for (int mt = 0; mt < 4; mt++) {
        #pragma unroll
        for (int nt = 0; nt < 4; nt++) {
            int r = row0 + wm * 64 + mt * 16 + qr;
            int c = col0 + wn * 32 + nt * 8 + qk;
            float b0 = bias ? bias[c] * alpha : 0.f;
            float b1 = bias ? bias[c + 1] * alpha : 0.f;
            float v0 = acc[mt][nt][0] * alpha + b0;
            float v1 = acc[mt][nt][1] * alpha + b1;
            float v2 = acc[mt][nt][2] * alpha + b0;
            float v3 = acc[mt][nt][3] * alpha + b1;
            if (EPI == 0) {
                *(float2*)&Cf[(size_t)r * ldc + c]       = make_float2(v0, v1);
                *(float2*)&Cf[(size_t)(r + 8) * ldc + c] = make_float2(v2, v3);
            } else {
                float h0 = __bfloat162float(__float2bfloat16(v0));
                float h1 = __bfloat162float(__float2bfloat16(v1));
                float h2 = __bfloat162float(__float2bfloat16(v2));
                float h3 = __bfloat162float(__float2bfloat16(v3));
                *(uint32_t*)&CH[(size_t)r * ldc + c]       = pack2(h0, h1);
                *(uint32_t*)&CH[(size_t)(r + 8) * ldc + c] = pack2(h2, h3);
                *(uint32_t*)&CL[(size_t)r * ldc + c]       = pack2(v0 - h0, v1 - h1);
                *(uint32_t*)&CL[(size_t)(r + 8) * ldc + c] = pack2(v2 - h2, v3 - h3);
            }
        }
    }
}

// ---------------------------------------------------------------------------
// converts: fp32 -> split hi/lo bf16
__global__ __launch_bounds__(256) void conv_in_kernel(
    const float4* __restrict__ q, const float4* __restrict__ k,
    const float4* __restrict__ v)
{
    const int n4 = MT * DM / 4;
    int i = blockIdx.x * 256 + threadIdx.x;
    if (i >= n4) return;
    const float4* src = blockIdx.z == 0 ? q : blockIdx.z == 1 ? k : v;
    size_t dstOff = (size_t)blockIdx.z * 4 * MB_;
    float4 w = src[i];
    float h0 = __bfloat162float(__float2bfloat16(w.x));
    float h1 = __bfloat162float(__float2bfloat16(w.y));
    float h2 = __bfloat162float(__float2bfloat16(w.z));
    float h3 = __bfloat162float(__float2bfloat16(w.w));
    *(uint2*)&g_H[dstOff + (size_t)i * 4] =
        make_uint2(pack2(h0, h1), pack2(h2, h3));
    *(uint2*)&g_L[dstOff + (size_t)i * 4] =
        make_uint2(pack2(w.x - h0, w.y - h1), pack2(w.z - h2, w.w - h3));
}
__global__ __launch_bounds__(256) void conv_w_kernel(
    const float4* __restrict__ wq, const float4* __restrict__ wk,
    const float4* __restrict__ wv, const float4* __restrict__ wo)
{
    const int n4 = DM * DM / 4;
    int i = blockIdx.x * 256 + threadIdx.x;
    if (i >= n4) return;
    const float4* src = blockIdx.z == 0 ? wq : blockIdx.z == 1 ? wk
                      : blockIdx.z == 2 ? wv : wo;
    size_t dstOff = OFF_WQ + (size_t)blockIdx.z * MB_;
    float4 w = src[i];
    float h0 = __bfloat162float(__float2bfloat16(w.x));
    float h1 = __bfloat162float(__float2bfloat16(w.y));
    float h2 = __bfloat162float(__float2bfloat16(w.z));
    float h3 = __bfloat162float(__float2bfloat16(w.w));
    *(uint2*)&g_H[dstOff + (size_t)i * 4] =
        make_uint2(pack2(h0, h1), pack2(h2, h3));
    *(uint2*)&g_L[dstOff + (size_t)i * 4] =
        make_uint2(pack2(w.x - h0, w.y - h1), pack2(w.z - h2, w.w - h3));
}

// ---------------------------------------------------------------------------
// QKV projections, one launch (z = 0/1/2). Q output pre-scaled by 1/8.
__global__ __launch_bounds__(256, 1) void proj_qkv_kernel(
    const float* __restrict__ bq, const float* __restrict__ bk,
    const float* __restrict__ bv)
{
    const int z = blockIdx.z;
    const float* bias = z == 0 ? bq : z == 1 ? bk : bv;
    const float alpha = z == 0 ? 0.125f : 1.0f;
    size_t aoff = (size_t)z * 4 * MB_;
    size_t boff = OFF_WQ + (size_t)z * MB_;
    size_t coff = OFF_QP + (size_t)z * 4 * MB_;
    gemm2<128, 128, 256, 1>(
        g_H + aoff, g_L + aoff, DM, g_H + boff, g_L + boff, DM,
        nullptr, g_H + coff, g_L + coff, DM, DM, alpha, bias);
}
// output projection
__global__ __launch_bounds__(256, 1) void proj_o_kernel(
    const float* __restrict__ bias, float* __restrict__ out)
{
    gemm2<128, 128, 256, 0>(
        g_H + OFF_OH, g_L + OFF_OH, DM,
        g_H + OFF_WQ + 3 * MB_, g_L + OFF_WQ + 3 * MB_, DM,
        out, nullptr, nullptr, DM, DM, 1.f, bias);
}

// ---------------------------------------------------------------------------
// Fused flash attention: scores + softmax + AV. Writes attn (fp32) and
// Oh (split bf16). grid (16 strips, 32 bh), 256 threads (8 warps x 16 rows).
// ---------------------------------------------------------------------------
// smem byte offsets
#define SQH 0
#define SQL 16384
#define SKH 32768
#define SKL 65536
#define SVH 98304
#define SVL 131072
#define SMREC 163840
#define ATTN_SMEM 172032

__global__ __launch_bounds__(256, 1) void attn_kernel(float* __restrict__ attn)
{
    extern __shared__ char sm[];
    float* mrec = (float*)(sm + SMREC);   // [16 ct][128 rows]

    const int tid  = threadIdx.x;
    const int wid  = tid >> 5, lane = tid & 31;
    const int qr   = lane >> 2, qk = lane & 3;
    const int strip = blockIdx.x;
    const int bh = blockIdx.y, b = bh >> 4, h = bh & 15;

    const size_t qrow0 = (size_t)b * SEQ + strip * 128;
    const size_t krow0 = (size_t)b * SEQ;
    const int    hc    = h * DK;
    float* attnB = attn + (size_t)bh * SEQ * SEQ + (size_t)strip * 128 * SEQ;

    // ---- fills ----
    auto fillQ = [&]() {
        #pragma unroll
        for (int it = 0; it < 8; it++) {
            int id = tid + it * 256;
            int arr = id >> 10, id2 = id & 1023;
            int r = id2 >> 3, c = id2 & 7;
            const bf16* src = (arr ? g_L : g_H) + OFF_QP +
                              (qrow0 + r) * DM + hc + c * 8;
            char* dst = sm + (arr ? SQL : SQH) + r * 128 + ((c ^ (r & 7)) << 4);
            CP16(smem_u32(dst), src);
        }
    };
    auto fillKV = [&](int ct, int buf) {
        #pragma unroll
        for (int it = 0; it < 16; it++) {
            int id = tid + it * 256;
            int which = id >> 11;            // 0=K 1=V
            int rem = id & 2047;
            int arr = rem >> 10, id2 = rem & 1023;
            int r = id2 >> 3, c = id2 & 7;
            size_t base = which ? OFF_VP : OFF_KP;
            const bf16* src = (arr ? g_L : g_H) + base +
                              (krow0 + ct * 128 + r) * DM + hc + c * 8;
            int sbase = which ? (arr ? SVL : SVH) : (arr ? SKL : SKH);
            char* dst = sm + sbase + buf * 16384 + r * 128 + ((c ^ (r & 7)) << 4);
            CP16(smem_u32(dst), src);
        }
    };

    fillQ(); CP_COMMIT();
    fillKV(0, 0); CP_COMMIT();

    // per-thread state
    float m0 = -1e30f, m1 = -1e30f, s0 = 0.f, s1 = 0.f;
    float vacc[8][4];
    #pragma unroll
    for (int i = 0; i < 8; i++)
        #pragma unroll
        for (int d = 0; d < 4; d++) vacc[i][d] = 0.f;

    uint32_t qh[4][4], ql[4][4];
    const int raL = lane & 15, chA = lane >> 4;

    for (int ct = 0; ct < 16; ct++) {
        const int buf = ct & 1;
        if (ct + 1 < 16) { fillKV(ct + 1, buf ^ 1); CP_COMMIT(); CP_WAIT1(); }
        else             { CP_WAIT0(); }
        __syncthreads();

        if (ct == 0) {
            #pragma unroll
            for (int kc = 0; kc < 4; kc++) {
                int r = wid * 16 + raL;
                int ch = 2 * kc + chA;
                int off = r * 128 + ((ch ^ (r & 7)) << 4);
                ldsm4(qh[kc], smem_u32(sm + SQH + off));
                ldsm4(ql[kc], smem_u32(sm + SQL + off));
            }
        }

        // ---- scores: 16 rows x 128 cols per warp ----
        float sacc[16][4];
        #pragma unroll
        for (int nt = 0; nt < 16; nt++)
            #pragma unroll
            for (int d = 0; d < 4; d++) sacc[nt][d] = 0.f;

        #pragma unroll
        for (int kc = 0; kc < 4; kc++) {
            #pragma unroll
            for (int np = 0; np < 8; np++) {
                int n = np * 16 + raL;
                int ch = 2 * kc + chA;
                int off = buf * 16384 + n * 128 + ((ch ^ (n & 7)) << 4);
                uint32_t th[4], tl[4];
                ldsm4(th, smem_u32(sm + SKH + off));
                ldsm4(tl, smem_u32(sm + SKL + off));
                #pragma unroll
                for (int j = 0; j < 2; j++) {
                    uint32_t bh2[2] = {th[j], th[2 + j]};
                    uint32_t bl2[2] = {tl[j], tl[2 + j]};
                    mma_bf16(sacc[np*2+j], qh[kc], bh2);
                    mma_bf16(sacc[np*2+j], qh[kc], bl2);
                    mma_bf16(sacc[np*2+j], ql[kc], bh2);
                }
            }
        }

        // ---- row max (2 rows/thread) ----
        float tm0 = -1e30f, tm1 = -1e30f;
        #pragma unroll
        for (int nt = 0; nt < 16; nt++) {
            tm0 = fmaxf(tm0, fmaxf(sacc[nt][0], sacc[nt][1]));
            tm1 = fmaxf(tm1, fmaxf(sacc[nt][2], sacc[nt][3]));
        }
        tm0 = fmaxf(tm0, __shfl_xor_sync(0xffffffffu, tm0, 1));
        tm0 = fmaxf(tm0, __shfl_xor_sync(0xffffffffu, tm0, 2));
        tm1 = fmaxf(tm1, __shfl_xor_sync(0xffffffffu, tm1, 1));
        tm1 = fmaxf(tm1, __shfl_xor_sync(0xffffffffu, tm1, 2));
        float mn0 = fmaxf(m0, tm0), mn1 = fmaxf(m1, tm1);
        float sf0 = __expf(m0 - mn0), sf1 = __expf(m1 - mn1);

        // ---- e = exp(x - m_new), write unnormalized, row sums ----
        float rs0 = 0.f, rs1 = 0.f;
        const int r0 = wid * 16 + qr;
        float* a0 = attnB + (size_t)r0 * SEQ + ct * 128 + qk * 2;
        float* a1 = attnB + (size_t)(r0 + 8) * SEQ + ct * 128 + qk * 2;
        #pragma unroll
        for (int nt = 0; nt < 16; nt++) {
            float e0 = __expf(sacc[nt][0] - mn0);
            float e1 = __expf(sacc[nt][1] - mn0);
            float e2 = __expf(sacc[nt][2] - mn1);
            float e3 = __expf(sacc[nt][3] - mn1);
            rs0 += e0 + e1; rs1 += e2 + e3;
            *(float2*)(a0 + nt * 8) = make_float2(e0, e1);
            *(float2*)(a1 + nt * 8) = make_float2(e2, e3);
            sacc[nt][0] = e0; sacc[nt][1] = e1;
            sacc[nt][2] = e2; sacc[nt][3] = e3;
        }
        rs0 += __shfl_xor_sync(0xffffffffu, rs0, 1);
        rs0 += __shfl_xor_sync(0xffffffffu, rs0, 2);
        rs1 += __shfl_xor_sync(0xffffffffu, rs1, 1);
        rs1 += __shfl_xor_sync(0xffffffffu, rs1, 2);
        s0 = s0 * sf0 + rs0;
        s1 = s1 * sf1 + rs1;
        m0 = mn0; m1 = mn1;
        if (qk == 0) { mrec[ct * 128 + r0] = mn0; mrec[ct * 128 + r0 + 8] = mn1; }

        // ---- rescale V-acc, then AV MMA ----
        #pragma unroll
        for (int nv = 0; nv < 8; nv++) {
            vacc[nv][0] *= sf0; vacc[nv][1] *= sf0;
            vacc[nv][2] *= sf1; vacc[nv][3] *= sf1;
        }
        #pragma unroll
        for (int kc2 = 0; kc2 < 8; kc2++) {
            // A-fragments built directly from e registers
            float e00 = sacc[2*kc2][0],   e01 = sacc[2*kc2][1];
            float e02 = sacc[2*kc2][2],   e03 = sacc[2*kc2][3];
            float e10 = sacc[2*kc2+1][0], e11 = sacc[2*kc2+1][1];
            float e12 = sacc[2*kc2+1][2], e13 = sacc[2*kc2+1][3];
            float h00 = __bfloat162float(__float2bfloat16(e00));
            float h01 = __bfloat162float(__float2bfloat16(e01));
            float h02 = __bfloat162float(__float2bfloat16(e02));
            float h03 = __bfloat162float(__float2bfloat16(e03));
            float h10 = __bfloat162float(__float2bfloat16(e10));
            float h11 = __bfloat162float(__float2bfloat16(e11));
            float h12 = __bfloat162float(__float2bfloat16(e12));
            float h13 = __bfloat162float(__float2bfloat16(e13));
            uint32_t ah[4] = { pack2(h00, h01), pack2(h02, h03),
                               pack2(h10, h11), pack2(h12, h13) };
            uint32_t al[4] = { pack2(e00 - h00, e01 - h01),
                               pack2(e02 - h02, e03 - h03),
                               pack2(e10 - h10, e11 - h11),
                               pack2(e12 - h12, e13 - h13) };
            #pragma unroll
            for (int dp = 0; dp < 4; dp++) {
                int kr = kc2 * 16 + (lane & 7) + chA * 8;
                int nch = dp * 2 + ((lane >> 3) & 1);
                int off = buf * 16384 + kr * 128 + ((nch ^ (kr & 7)) << 4);
                uint32_t tvh[4], tvl[4];
                ldsm4t(tvh, smem_u32(sm + SVH + off));
                ldsm4t(tvl, smem_u32(sm + SVL + off));
                #pragma unroll
                for (int j = 0; j < 2; j++) {
                    uint32_t bvh[2] = {tvh[j], tvh[2 + j]};
                    uint32_t bvl[2] = {tvl[j], tvl[2 + j]};
                    mma_bf16(vacc[dp*2+j], ah, bvh);
                    mma_bf16(vacc[dp*2+j], ah, bvl);
                    mma_bf16(vacc[dp*2+j], al, bvh);
                }
            }
        }
        __syncthreads();
    }

    // ---- write Oh (split bf16) ----
    {
        float iv0 = 1.f / s0, iv1 = 1.f / s1;
        const int r0l = wid * 16 + qr;
        size_t rg0 = (qrow0 + r0l) * DM + hc;
        size_t rg1 = (qrow0 + r0l + 8) * DM + hc;
        #pragma unroll
        for (int nv = 0; nv < 8; nv++) {
            int c = nv * 8 + qk * 2;
            float v0 = vacc[nv][0] * iv0, v1 = vacc[nv][1] * iv0;
            float v2 = vacc[nv][2] * iv1, v3 = vacc[nv][3] * iv1;
            float h0 = __bfloat162float(__float2bfloat16(v0));
            float h1 = __bfloat162float(__float2bfloat16(v1));
            float h2 = __bfloat162float(__float2bfloat16(v2));
            float h3 = __bfloat162float(__float2bfloat16(v3));
            *(uint32_t*)&g_H[OFF_OH + rg0 + c] = pack2(h0, h1);
            *(uint32_t*)&g_H[OFF_OH + rg1 + c] = pack2(h2, h3);
            *(uint32_t*)&g_L[OFF_OH + rg0 + c] = pack2(v0 - h0, v1 - h1);
            *(uint32_t*)&g_L[OFF_OH + rg1 + c] = pack2(v2 - h2, v3 - h3);
        }
    }

    __syncthreads();   // mrec visible

    // ---- phase 2: normalize attn in place ----
    {
        float iv0 = 1.f / s0, iv1 = 1.f / s1;
        const int r0 = wid * 16 + qr;
        #pragma unroll 1
        for (int ct = 0; ct < 16; ct++) {
            float c0 = __expf(mrec[ct * 128 + r0] - m0) * iv0;
            float c1 = __expf(mrec[ct * 128 + r0 + 8] - m1) * iv1;
            float* a0 = attnB + (size_t)r0 * SEQ + ct * 128 + qk * 2;
            float* a1 = attnB + (size_t)(r0 + 8) * SEQ + ct * 128 + qk * 2;
            #pragma unroll
            for (int nt = 0; nt < 16; nt++) {
                float2 t0 = *(float2*)(a0 + nt * 8);
                float2 t1 = *(float2*)(a1 + nt * 8);
                t0.x *= c0; t0.y *= c0; t1.x *= c1; t1.y *= c1;
                *(float2*)(a0 + nt * 8) = t0;
                *(float2*)(a1 + nt * 8) = t1;
            }
        }
    }
}

// ---------------------------------------------------------------------------
extern "C" void kernel_launch(void* const* d_in, const int* in_sizes, int n_in,
                              void* d_out, int out_size)
{
    const float* q  = (const float*)d_in[0];
    const float* k  = (const float*)d_in[1];
    const float* v  = (const float*)d_in[2];
    const float* wq = (const float*)d_in[3];
    const float* bq = (const float*)d_in[4];
    const float* wk = (const float*)d_in[5];
    const float* bk = (const float*)d_in[6];
    const float* wv = (const float*)d_in[7];
    const float* bv = (const float*)d_in[8];
    const float* wo = (const float*)d_in[9];
    const float* bo = (const float*)d_in[10];

    float* out  = (float*)d_out;
    float* attn = out + (size_t)MT * DM;

    static bool attrSet = false;
    if (!attrSet) {
        cudaFuncSetAttribute(proj_qkv_kernel,
            cudaFuncAttributeMaxDynamicSharedMemorySize, 65536);
        cudaFuncSetAttribute(proj_o_kernel,
            cudaFuncAttributeMaxDynamicSharedMemorySize, 65536);
        cudaFuncSetAttribute(attn_kernel,
            cudaFuncAttributeMaxDynamicSharedMemorySize, ATTN_SMEM);
        attrSet = true;
    }

    conv_in_kernel<<<dim3(MT * DM / 4 / 256, 1, 3), 256>>>(
        (const float4*)q, (const float4*)k, (const float4*)v);
    conv_w_kernel<<<dim3(DM * DM / 4 / 256, 1, 4), 256>>>(
        (const float4*)wq, (const float4*)wk, (const float4*)wv,
        (const float4*)wo);

    proj_qkv_kernel<<<dim3(DM / 128, MT / 128, 3), 256, 65536>>>(bq, bk, bv);

    attn_kernel<<<dim3(SEQ / 128, BATCH * NH), 256, ATTN_SMEM>>>(attn);

    proj_o_kernel<<<dim3(DM / 128, MT / 128), 256, 65536>>>(bo, out);
}

// round 10
// speedup vs baseline: 2.4588x; 1.0136x over previous
#include <cuda_runtime.h>
#include <cuda_bf16.h>
#include <cstdint>

#define BATCH 2
#define SEQ   2048
#define DM    1024
#define NH    16
#define DK    64
#define MT    (BATCH*SEQ)

typedef __nv_bfloat16 bf16;

constexpr size_t MB_   = 1024 * 1024;
constexpr size_t OFF_Q  = 0;
constexpr size_t OFF_K  = 4 * MB_;
constexpr size_t OFF_V  = 8 * MB_;
constexpr size_t OFF_WQ = 12 * MB_;
constexpr size_t OFF_QP = 16 * MB_;
constexpr size_t OFF_KP = 20 * MB_;
constexpr size_t OFF_VP = 24 * MB_;
constexpr size_t OFF_OH = 28 * MB_;
constexpr size_t TOTEL  = 32 * MB_;

__device__ bf16 g_H[TOTEL];
__device__ bf16 g_L[TOTEL];

// ---------------------------------------------------------------------------
__device__ __forceinline__ uint32_t smem_u32(const void* p)
{ return (uint32_t)__cvta_generic_to_shared(p); }
#define CP16(dst, src) \
    asm volatile("cp.async.cg.shared.global [%0], [%1], 16;" :: "r"(dst), "l"(src))
#define CP_COMMIT() asm volatile("cp.async.commit_group;")
#define CP_WAIT1()  asm volatile("cp.async.wait_group 1;")
#define CP_WAIT0()  asm volatile("cp.async.wait_group 0;")

__device__ __forceinline__ void ldsm4(uint32_t* r, uint32_t a)
{
    asm volatile("ldmatrix.sync.aligned.m8n8.x4.shared.b16 {%0,%1,%2,%3}, [%4];"
                 : "=r"(r[0]), "=r"(r[1]), "=r"(r[2]), "=r"(r[3]) : "r"(a));
}
__device__ __forceinline__ void ldsm4t(uint32_t* r, uint32_t a)
{
    asm volatile("ldmatrix.sync.aligned.m8n8.x4.trans.shared.b16 {%0,%1,%2,%3}, [%4];"
                 : "=r"(r[0]), "=r"(r[1]), "=r"(r[2]), "=r"(r[3]) : "r"(a));
}
__device__ __forceinline__ void mma_bf16(
    float* d, const uint32_t* a, const uint32_t* b)
{
    asm volatile(
        "mma.sync.aligned.m16n8k16.row.col.f32.bf16.bf16.f32 "
        "{%0,%1,%2,%3}, {%4,%5,%6,%7}, {%8,%9}, {%0,%1,%2,%3};"
        : "+f"(d[0]), "+f"(d[1]), "+f"(d[2]), "+f"(d[3])
        : "r"(a[0]), "r"(a[1]), "r"(a[2]), "r"(a[3]), "r"(b[0]), "r"(b[1]));
}
__device__ __forceinline__ uint32_t pack2(float x, float y)
{
    __nv_bfloat162 t = __floats2bfloat162_rn(x, y);
    return *(uint32_t*)&t;
}

// ---------------------------------------------------------------------------
// bf16x3 GEMM for projections (pre-split operands, cp.async double-buffer)
// ---------------------------------------------------------------------------
template<int BM, int BN, int NT, int EPI>
__device__ __forceinline__ void gemm2(
    const bf16* __restrict__ AH, const bf16* __restrict__ AL, int lda,
    const bf16* __restrict__ BH, const bf16* __restrict__ BL, int ldb,
    float* __restrict__ Cf, bf16* __restrict__ CH, bf16* __restrict__ CL,
    int ldc, int K, float alpha, const float* __restrict__ bias)
{
    constexpr int WGM  = BM / 64;
    constexpr int ABUF = BM * 64;
    constexpr int BBUF = BN * 64;
    extern __shared__ char smem[];
    char* aHs = smem;
    char* aLs = aHs + 2 * ABUF;
    char* bHs = aLs + 2 * ABUF;
    char* bLs = bHs + 2 * BBUF;

    const int tid  = threadIdx.x;
    const int wid  = tid >> 5, lane = tid & 31;
    const int wm   = wid % WGM;
    const int wn   = wid / WGM;
    const int row0 = blockIdx.y * BM;
    const int col0 = blockIdx.x * BN;

    float acc[4][4][4];
    #pragma unroll
    for (int i = 0; i < 4; i++)
        #pragma unroll
        for (int j = 0; j < 4; j++)
            #pragma unroll
            for (int d = 0; d < 4; d++) acc[i][j][d] = 0.f;

    const int raL = lane & 15;
    const int chA = lane >> 4;

    auto fillA = [&](int kt, int buf) {
        constexpr int ACH = BM * 4;
        #pragma unroll
        for (int it = 0; it < (2 * ACH) / NT; it++) {
            int id  = tid + it * NT;
            int arr = id / ACH, id2 = id % ACH;
            int r = id2 >> 2, c = id2 & 3;
            const bf16* src = (arr ? AL : AH) + (size_t)(row0 + r) * lda + kt + c * 8;
            char* dst = (arr ? aLs : aHs) + buf * ABUF + r * 64 + ((c ^ ((r >> 1) & 3)) << 4);
            CP16(smem_u32(dst), src);
        }
    };
    auto fillB = [&](int kt, int buf) {
        constexpr int BCH = BN * 4;
        #pragma unroll
        for (int it = 0; it < (2 * BCH) / NT; it++) {
            int id  = tid + it * NT;
            int arr = id / BCH, id2 = id % BCH;
            int r = id2 >> 2, c = id2 & 3;
            const bf16* src = (arr ? BL : BH) + (size_t)(col0 + r) * ldb + kt + c * 8;
            char* dst = (arr ? bLs : bHs) + buf * BBUF + r * 64 + ((c ^ ((r >> 1) & 3)) << 4);
            CP16(smem_u32(dst), src);
        }
    };

    const int nIter = K / 32;
    fillA(0, 0); fillB(0, 0); CP_COMMIT();

    for (int i = 0; i < nIter; i++) {
        const int buf = i & 1;
        if (i + 1 < nIter) {
            fillA((i + 1) * 32, buf ^ 1);
            fillB((i + 1) * 32, buf ^ 1);
            CP_COMMIT();
            CP_WAIT1();
        } else { CP_WAIT0(); }
        __syncthreads();

        #pragma unroll
        for (int ks = 0; ks < 32; ks += 16) {
            const int kc = ks >> 3;
            uint32_t ah[4][4], al[4][4], bh[4][2], bl[4][2];
            #pragma unroll
            for (int mt = 0; mt < 4; mt++) {
                int r  = wm * 64 + mt * 16 + raL;
                int ca = kc + chA;
                int off = buf * ABUF + r * 64 + ((ca ^ ((r >> 1) & 3)) << 4);
                ldsm4(ah[mt], smem_u32(aHs + off));
                ldsm4(al[mt], smem_u32(aLs + off));
            }
            #pragma unroll
            for (int np = 0; np < 2; np++) {
                uint32_t t4[4], u4[4];
                int n  = wn * 32 + np * 16 + raL;
                int cb = kc + chA;
                int off = buf * BBUF + n * 64 + ((cb ^ ((n >> 1) & 3)) << 4);
                ldsm4(t4, smem_u32(bHs + off));
                ldsm4(u4, smem_u32(bLs + off));
                bh[np*2][0]   = t4[0]; bh[np*2+1][0] = t4[1];
                bh[np*2][1]   = t4[2]; bh[np*2+1][1] = t4[3];
                bl[np*2][0]   = u4[0]; bl[np*2+1][0] = u4[1];
                bl[np*2][1]   = u4[2]; bl[np*2+1][1] = u4[3];
            }
            #pragma unroll
            for (int mt = 0; mt < 4; mt++)
                #pragma unroll
                for (int nt = 0; nt < 4; nt++) {
                    mma_bf16(acc[mt][nt], ah[mt], bh[nt]);
                    mma_bf16(acc[mt][nt], ah[mt], bl[nt]);
                    mma_bf16(acc[mt][nt], al[mt], bh[nt]);
                }
        }
        __syncthreads();
    }

    const int qr = lane >> 2, qk = (lane & 3) * 2;
    #pragma unroll
    for (int mt = 0; mt < 4; mt++) {
        #pragma unroll
        for (int nt = 0; nt < 4; nt++) {
            int r = row0 + wm * 64 + mt * 16 + qr;
            int c = col0 + wn * 32 + nt * 8 + qk;
            float b0 = bias ? bias[c] * alpha : 0.f;
            float b1 = bias ? bias[c + 1] * alpha : 0.f;
            float v0 = acc[mt][nt][0] * alpha + b0;
            float v1 = acc[mt][nt][1] * alpha + b1;
            float v2 = acc[mt][nt][2] * alpha + b0;
            float v3 = acc[mt][nt][3] * alpha + b1;
            if (EPI == 0) {
                *(float2*)&Cf[(size_t)r * ldc + c]       = make_float2(v0, v1);
                *(float2*)&Cf[(size_t)(r + 8) * ldc + c] = make_float2(v2, v3);
            } else {
                float h0 = __bfloat162float(__float2bfloat16(v0));
                float h1 = __bfloat162float(__float2bfloat16(v1));
                float h2 = __bfloat162float(__float2bfloat16(v2));
                float h3 = __bfloat162float(__float2bfloat16(v3));
                *(uint32_t*)&CH[(size_t)r * ldc + c]       = pack2(h0, h1);
                *(uint32_t*)&CH[(size_t)(r + 8) * ldc + c] = pack2(h2, h3);
                *(uint32_t*)&CL[(size_t)r * ldc + c]       = pack2(v0 - h0, v1 - h1);
                *(uint32_t*)&CL[(size_t)(r + 8) * ldc + c] = pack2(v2 - h2, v3 - h3);
            }
        }
    }
}

// ---------------------------------------------------------------------------
__global__ __launch_bounds__(256) void conv_in_kernel(
    const float4* __restrict__ q, const float4* __restrict__ k,
    const float4* __restrict__ v)
{
    const int n4 = MT * DM / 4;
    int i = blockIdx.x * 256 + threadIdx.x;
    if (i >= n4) return;
    const float4* src = blockIdx.z == 0 ? q : blockIdx.z == 1 ? k : v;
    size_t dstOff = (size_t)blockIdx.z * 4 * MB_;
    float4 w = src[i];
    float h0 = __bfloat162float(__float2bfloat16(w.x));
    float h1 = __bfloat162float(__float2bfloat16(w.y));
    float h2 = __bfloat162float(__float2bfloat16(w.z));
    float h3 = __bfloat162float(__float2bfloat16(w.w));
    *(uint2*)&g_H[dstOff + (size_t)i * 4] =
        make_uint2(pack2(h0, h1), pack2(h2, h3));
    *(uint2*)&g_L[dstOff + (size_t)i * 4] =
        make_uint2(pack2(w.x - h0, w.y - h1), pack2(w.z - h2, w.w - h3));
}
__global__ __launch_bounds__(256) void conv_w_kernel(
    const float4* __restrict__ wq, const float4* __restrict__ wk,
    const float4* __restrict__ wv, const float4* __restrict__ wo)
{
    const int n4 = DM * DM / 4;
    int i = blockIdx.x * 256 + threadIdx.x;
    if (i >= n4) return;
    const float4* src = blockIdx.z == 0 ? wq : blockIdx.z == 1 ? wk
                      : blockIdx.z == 2 ? wv : wo;
    size_t dstOff = OFF_WQ + (size_t)blockIdx.z * MB_;
    float4 w = src[i];
    float h0 = __bfloat162float(__float2bfloat16(w.x));
    float h1 = __bfloat162float(__float2bfloat16(w.y));
    float h2 = __bfloat162float(__float2bfloat16(w.z));
    float h3 = __bfloat162float(__float2bfloat16(w.w));
    *(uint2*)&g_H[dstOff + (size_t)i * 4] =
        make_uint2(pack2(h0, h1), pack2(h2, h3));
    *(uint2*)&g_L[dstOff + (size_t)i * 4] =
        make_uint2(pack2(w.x - h0, w.y - h1), pack2(w.z - h2, w.w - h3));
}

// ---------------------------------------------------------------------------
__global__ __launch_bounds__(256, 1) void proj_qkv_kernel(
    const float* __restrict__ bq, const float* __restrict__ bk,
    const float* __restrict__ bv)
{
    const int z = blockIdx.z;
    const float* bias = z == 0 ? bq : z == 1 ? bk : bv;
    const float alpha = z == 0 ? 0.125f : 1.0f;
    size_t aoff = (size_t)z * 4 * MB_;
    size_t boff = OFF_WQ + (size_t)z * MB_;
    size_t coff = OFF_QP + (size_t)z * 4 * MB_;
    gemm2<128, 128, 256, 1>(
        g_H + aoff, g_L + aoff, DM, g_H + boff, g_L + boff, DM,
        nullptr, g_H + coff, g_L + coff, DM, DM, alpha, bias);
}
__global__ __launch_bounds__(256, 1) void proj_o_kernel(
    const float* __restrict__ bias, float* __restrict__ out)
{
    gemm2<128, 128, 256, 0>(
        g_H + OFF_OH, g_L + OFF_OH, DM,
        g_H + OFF_WQ + 3 * MB_, g_L + OFF_WQ + 3 * MB_, DM,
        out, nullptr, nullptr, DM, DM, 1.f, bias);
}

// ---------------------------------------------------------------------------
// Fused flash attention, two-pass (stats, then write+AV), single attn write.
// grid (16 strips, 32 bh), 256 threads.
// ---------------------------------------------------------------------------
#define SQH 0
#define SQL 16384
#define SKH 32768
#define SKL 65536
#define SVH 98304
#define SVL 131072
#define ATTN_SMEM 163840

__global__ __launch_bounds__(256, 1) void attn_kernel(float* __restrict__ attn)
{
    extern __shared__ char sm[];

    const int tid  = threadIdx.x;
    const int wid  = tid >> 5, lane = tid & 31;
    const int qr   = lane >> 2, qk = lane & 3;
    const int strip = blockIdx.x;
    const int bh = blockIdx.y, b = bh >> 4, h = bh & 15;

    const size_t qrow0 = (size_t)b * SEQ + strip * 128;
    const size_t krow0 = (size_t)b * SEQ;
    const int    hc    = h * DK;
    float* attnB = attn + (size_t)bh * SEQ * SEQ + (size_t)strip * 128 * SEQ;

    auto fillQ = [&]() {
        #pragma unroll
        for (int it = 0; it < 8; it++) {
            int id = tid + it * 256;
            int arr = id >> 10, id2 = id & 1023;
            int r = id2 >> 3, c = id2 & 7;
            const bf16* src = (arr ? g_L : g_H) + OFF_QP +
                              (qrow0 + r) * DM + hc + c * 8;
            char* dst = sm + (arr ? SQL : SQH) + r * 128 + ((c ^ (r & 7)) << 4);
            CP16(smem_u32(dst), src);
        }
    };
    auto fillK = [&](int ct, int buf) {
        #pragma unroll
        for (int it = 0; it < 8; it++) {
            int id = tid + it * 256;
            int arr = id >> 10, id2 = id & 1023;
            int r = id2 >> 3, c = id2 & 7;
            const bf16* src = (arr ? g_L : g_H) + OFF_KP +
                              (krow0 + ct * 128 + r) * DM + hc + c * 8;
            char* dst = sm + (arr ? SKL : SKH) + buf * 16384 + r * 128 + ((c ^ (r & 7)) << 4);
            CP16(smem_u32(dst), src);
        }
    };
    auto fillV = [&](int ct, int buf) {
        #pragma unroll
        for (int it = 0; it < 8; it++) {
            int id = tid + it * 256;
            int arr = id >> 10, id2 = id & 1023;
            int r = id2 >> 3, c = id2 & 7;
            const bf16* src = (arr ? g_L : g_H) + OFF_VP +
                              (krow0 + ct * 128 + r) * DM + hc + c * 8;
            char* dst = sm + (arr ? SVL : SVH) + buf * 16384 + r * 128 + ((c ^ (r & 7)) << 4);
            CP16(smem_u32(dst), src);
        }
    };

    fillQ(); CP_COMMIT();
    fillK(0, 0); CP_COMMIT();

    uint32_t qh[4][4], ql[4][4];
    const int raL = lane & 15, chA = lane >> 4;

    // compute scores for tile ct (buffer buf) into sacc
    auto scoresMMA = [&](int buf, float (*sacc)[4]) {
        #pragma unroll
        for (int nt = 0; nt < 16; nt++)
            #pragma unroll
            for (int d = 0; d < 4; d++) sacc[nt][d] = 0.f;
        #pragma unroll
        for (int kc = 0; kc < 4; kc++) {
            #pragma unroll
            for (int np = 0; np < 8; np++) {
                int n = np * 16 + raL;
                int ch = 2 * kc + chA;
                int off = buf * 16384 + n * 128 + ((ch ^ (n & 7)) << 4);
                uint32_t th[4], tl[4];
                ldsm4(th, smem_u32(sm + SKH + off));
                ldsm4(tl, smem_u32(sm + SKL + off));
                #pragma unroll
                for (int j = 0; j < 2; j++) {
                    uint32_t bh2[2] = {th[j], th[2 + j]};
                    uint32_t bl2[2] = {tl[j], tl[2 + j]};
                    mma_bf16(sacc[np*2+j], qh[kc], bh2);
                    mma_bf16(sacc[np*2+j], qh[kc], bl2);
                    mma_bf16(sacc[np*2+j], ql[kc], bh2);
                }
            }
        }
    };

    // ---------------- pass 1: row max + sum ----------------
    float m0 = -1e30f, m1 = -1e30f, s0 = 0.f, s1 = 0.f;
    for (int ct = 0; ct < 16; ct++) {
        const int buf = ct & 1;
        if (ct + 1 < 16) { fillK(ct + 1, buf ^ 1); CP_COMMIT(); CP_WAIT1(); }
        else             { CP_WAIT0(); }
        __syncthreads();

        if (ct == 0) {
            #pragma unroll
            for (int kc = 0; kc < 4; kc++) {
                int r = wid * 16 + raL;
                int ch = 2 * kc + chA;
                int off = r * 128 + ((ch ^ (r & 7)) << 4);
                ldsm4(qh[kc], smem_u32(sm + SQH + off));
                ldsm4(ql[kc], smem_u32(sm + SQL + off));
            }
        }

        float sacc[16][4];
        scoresMMA(buf, sacc);

        float tm0 = -1e30f, tm1 = -1e30f;
        #pragma unroll
        for (int nt = 0; nt < 16; nt++) {
            tm0 = fmaxf(tm0, fmaxf(sacc[nt][0], sacc[nt][1]));
            tm1 = fmaxf(tm1, fmaxf(sacc[nt][2], sacc[nt][3]));
        }
        tm0 = fmaxf(tm0, __shfl_xor_sync(0xffffffffu, tm0, 1));
        tm0 = fmaxf(tm0, __shfl_xor_sync(0xffffffffu, tm0, 2));
        tm1 = fmaxf(tm1, __shfl_xor_sync(0xffffffffu, tm1, 1));
        tm1 = fmaxf(tm1, __shfl_xor_sync(0xffffffffu, tm1, 2));
        float mn0 = fmaxf(m0, tm0), mn1 = fmaxf(m1, tm1);
        float sf0 = __expf(m0 - mn0), sf1 = __expf(m1 - mn1);

        float rs0 = 0.f, rs1 = 0.f;
        #pragma unroll
        for (int nt = 0; nt < 16; nt++) {
            rs0 += __expf(sacc[nt][0] - mn0) + __expf(sacc[nt][1] - mn0);
            rs1 += __expf(sacc[nt][2] - mn1) + __expf(sacc[nt][3] - mn1);
        }
        rs0 += __shfl_xor_sync(0xffffffffu, rs0, 1);
        rs0 += __shfl_xor_sync(0xffffffffu, rs0, 2);
        rs1 += __shfl_xor_sync(0xffffffffu, rs1, 1);
        rs1 += __shfl_xor_sync(0xffffffffu, rs1, 2);
        s0 = s0 * sf0 + rs0;
        s1 = s1 * sf1 + rs1;
        m0 = mn0; m1 = mn1;
        __syncthreads();
    }

    const float iv0 = 1.f / s0, iv1 = 1.f / s1;

    // ---------------- pass 2: normalized write + AV ----------------
    float vacc[8][4];
    #pragma unroll
    for (int i = 0; i < 8; i++)
        #pragma unroll
        for (int d = 0; d < 4; d++) vacc[i][d] = 0.f;

    fillK(0, 0); fillV(0, 0); CP_COMMIT();

    for (int ct = 0; ct < 16; ct++) {
        const int buf = ct & 1;
        if (ct + 1 < 16) {
            fillK(ct + 1, buf ^ 1); fillV(ct + 1, buf ^ 1);
            CP_COMMIT(); CP_WAIT1();
        } else { CP_WAIT0(); }
        __syncthreads();

        float sacc[16][4];
        scoresMMA(buf, sacc);

        // normalized probabilities; write attn once (streaming)
        const int r0 = wid * 16 + qr;
        float* a0 = attnB + (size_t)r0 * SEQ + ct * 128 + qk * 2;
        float* a1 = attnB + (size_t)(r0 + 8) * SEQ + ct * 128 + qk * 2;
        #pragma unroll
        for (int nt = 0; nt < 16; nt++) {
            float p0 = __expf(sacc[nt][0] - m0) * iv0;
            float p1 = __expf(sacc[nt][1] - m0) * iv0;
            float p2 = __expf(sacc[nt][2] - m1) * iv1;
            float p3 = __expf(sacc[nt][3] - m1) * iv1;
            __stcs((float2*)(a0 + nt * 8), make_float2(p0, p1));
            __stcs((float2*)(a1 + nt * 8), make_float2(p2, p3));
            sacc[nt][0] = p0; sacc[nt][1] = p1;
            sacc[nt][2] = p2; sacc[nt][3] = p3;
        }

        // AV: A-fragments built from normalized probability registers
        #pragma unroll
        for (int kc2 = 0; kc2 < 8; kc2++) {
            float e00 = sacc[2*kc2][0],   e01 = sacc[2*kc2][1];
            float e02 = sacc[2*kc2][2],   e03 = sacc[2*kc2][3];
            float e10 = sacc[2*kc2+1][0], e11 = sacc[2*kc2+1][1];
            float e12 = sacc[2*kc2+1][2], e13 = sacc[2*kc2+1][3];
            float h00 = __bfloat162float(__float2bfloat16(e00));
            float h01 = __bfloat162float(__float2bfloat16(e01));
            float h02 = __bfloat162float(__float2bfloat16(e02));
            float h03 = __bfloat162float(__float2bfloat16(e03));
            float h10 = __bfloat162float(__float2bfloat16(e10));
            float h11 = __bfloat162float(__float2bfloat16(e11));
            float h12 = __bfloat162float(__float2bfloat16(e12));
            float h13 = __bfloat162float(__float2bfloat16(e13));
            uint32_t ah[4] = { pack2(h00, h01), pack2(h02, h03),
                               pack2(h10, h11), pack2(h12, h13) };
            uint32_t al[4] = { pack2(e00 - h00, e01 - h01),
                               pack2(e02 - h02, e03 - h03),
                               pack2(e10 - h10, e11 - h11),
                               pack2(e12 - h12, e13 - h13) };
            #pragma unroll
            for (int dp = 0; dp < 4; dp++) {
                int kr = kc2 * 16 + (lane & 7) + chA * 8;
                int nch = dp * 2 + ((lane >> 3) & 1);
                int off = buf * 16384 + kr * 128 + ((nch ^ (kr & 7)) << 4);
                uint32_t tvh[4], tvl[4];
                ldsm4t(tvh, smem_u32(sm + SVH + off));
                ldsm4t(tvl, smem_u32(sm + SVL + off));
                #pragma unroll
                for (int j = 0; j < 2; j++) {
                    uint32_t bvh[2] = {tvh[j], tvh[2 + j]};
                    uint32_t bvl[2] = {tvl[j], tvl[2 + j]};
                    mma_bf16(vacc[dp*2+j], ah, bvh);
                    mma_bf16(vacc[dp*2+j], ah, bvl);
                    mma_bf16(vacc[dp*2+j], al, bvh);
                }
            }
        }
        __syncthreads();
    }

    // ---- write Oh (split bf16); vacc already normalized ----
    {
        const int r0l = wid * 16 + qr;
        size_t rg0 = (qrow0 + r0l) * DM + hc;
        size_t rg1 = (qrow0 + r0l + 8) * DM + hc;
        #pragma unroll
        for (int nv = 0; nv < 8; nv++) {
            int c = nv * 8 + qk * 2;
            float v0 = vacc[nv][0], v1 = vacc[nv][1];
            float v2 = vacc[nv][2], v3 = vacc[nv][3];
            float h0 = __bfloat162float(__float2bfloat16(v0));
            float h1 = __bfloat162float(__float2bfloat16(v1));
            float h2 = __bfloat162float(__float2bfloat16(v2));
            float h3 = __bfloat162float(__float2bfloat16(v3));
            *(uint32_t*)&g_H[OFF_OH + rg0 + c] = pack2(h0, h1);
            *(uint32_t*)&g_H[OFF_OH + rg1 + c] = pack2(h2, h3);
            *(uint32_t*)&g_L[OFF_OH + rg0 + c] = pack2(v0 - h0, v1 - h1);
            *(uint32_t*)&g_L[OFF_OH + rg1 + c] = pack2(v2 - h2, v3 - h3);
        }
    }
}

// ---------------------------------------------------------------------------
extern "C" void kernel_launch(void* const* d_in, const int* in_sizes, int n_in,
                              void* d_out, int out_size)
{
    const float* q  = (const float*)d_in[0];
    const float* k  = (const float*)d_in[1];
    const float* v  = (const float*)d_in[2];
    const float* wq = (const float*)d_in[3];
    const float* bq = (const float*)d_in[4];
    const float* wk = (const float*)d_in[5];
    const float* bk = (const float*)d_in[6];
    const float* wv = (const float*)d_in[7];
    const float* bv = (const float*)d_in[8];
    const float* wo = (const float*)d_in[9];
    const float* bo = (const float*)d_in[10];

    float* out  = (float*)d_out;
    float* attn = out + (size_t)MT * DM;

    static bool attrSet = false;
    if (!attrSet) {
        cudaFuncSetAttribute(proj_qkv_kernel,
            cudaFuncAttributeMaxDynamicSharedMemorySize, 65536);
        cudaFuncSetAttribute(proj_o_kernel,
            cudaFuncAttributeMaxDynamicSharedMemorySize, 65536);
        cudaFuncSetAttribute(attn_kernel,
            cudaFuncAttributeMaxDynamicSharedMemorySize, ATTN_SMEM);
        attrSet = true;
    }

    conv_in_kernel<<<dim3(MT * DM / 4 / 256, 1, 3), 256>>>(
        (const float4*)q, (const float4*)k, (const float4*)v);
    conv_w_kernel<<<dim3(DM * DM / 4 / 256, 1, 4), 256>>>(
        (const float4*)wq, (const float4*)wk, (const float4*)wv,
        (const float4*)wo);

    proj_qkv_kernel<<<dim3(DM / 128, MT / 128, 3), 256, 65536>>>(bq, bk, bv);

    attn_kernel<<<dim3(SEQ / 128, BATCH * NH), 256, ATTN_SMEM>>>(attn);

    proj_o_kernel<<<dim3(DM / 128, MT / 128), 256, 65536>>>(bo, out);
}